// round 16
// baseline (speedup 1.0000x reference)
#include <cuda_runtime.h>
#include <cuda_bf16.h>

// ---------------------------------------------------------------------------
// B=4 batches, M=256 bins, N = in_sizes[0]/B particles.
// joint[b,i,j] = sum_n exp(-0.5((x-bins[i])/h)^2) * exp(-0.5((y-bins[j])/h)^2)
// out = joint / (sum_ij joint + 1e-10), h = bins[1]-bins[0].
//
// fp32 Gaussian support: term == 0 once |d|/h > 14.4 -> banded. Particles are
// pre-binned into per-(batch,tile) buckets (cut 14.6h, exact w.r.t. fp32
// underflow), 8-way segmented (128B-strided counters -> no L2 atomic
// serialization). tile_kernel is PERSISTENT: 608 CTAs (one wave) pull the
// 8192 segments off a global ticket -> no empty-CTA waves, free balance.
// ---------------------------------------------------------------------------

#define NBATCH 4
#define MDIM   256
#define TILE   16
#define NT     16        // tiles per axis
#define SPLIT  8         // segments per bucket
#define SEGCAP 2048      // per-segment capacity (hot segment ~1k bound)
#define BUF    256       // particles per chunk
#define CPAD   20        // 16 table entries + 4 pad floats
#define NBUCK  (NBATCH * NT * NT)
#define NSEG   (NBUCK * SPLIT)          // 8192
#define TGRID  608                      // 4 CTAs/SM x 152 SMs (one wave)

// Static scratch (load-time allocation; no runtime alloc).
__device__ float2 g_bucket[NSEG * SEGCAP];                 // ~134 MB
__device__ int    g_cnt[NSEG * 32];                        // 128B-strided ctrs
__device__ float  g_part[NBATCH * SPLIT * MDIM * MDIM];    // 8 MB partials
__device__ float  g_sum[NBATCH];
__device__ int    g_done;
__device__ int    g_ticket;

__device__ __forceinline__ float ex2f(float a) {
    float r;
    asm("ex2.approx.ftz.f32 %0, %1;" : "=f"(r) : "f"(a));
    return r;
}

// ---------------------------------------------------------------------------
__global__ void zero_kernel()
{
    const int t = blockIdx.x * 256 + threadIdx.x;
    if (t < NSEG)   g_cnt[t * 32] = 0;
    if (t < NBATCH) g_sum[t] = 0.f;
    if (t == NBATCH)     g_done = 0;
    if (t == NBATCH + 1) g_ticket = 0;
}

// ---------------------------------------------------------------------------
// One thread per particle: scatter (x,y) into every tile bucket whose window
// contains it (<=3x3 tiles). Tile i window (bin units t=(x-b0)/h):
//   i in [ceil((t-29.6)/16), floor((t+14.6)/16)].
__global__ void bin_kernel(const float* __restrict__ x,
                           const float* __restrict__ y,
                           const float* __restrict__ bins, int N)
{
    const int idx = blockIdx.x * 256 + threadIdx.x;
    const int b   = blockIdx.y;
    if (idx >= N) return;

    const float b0   = __ldg(bins);
    const float h    = __ldg(bins + 1) - b0;
    const float invh = 1.0f / h;

    const float xv = __ldg(x + b * N + idx);
    const float yv = __ldg(y + b * N + idx);
    const float tx = (xv - b0) * invh;
    const float ty = (yv - b0) * invh;

    const float s = 1.0f / 16.0f;
    const int ix0 = max(0,      (int)ceilf ((tx - 29.6f) * s));
    const int ix1 = min(NT - 1, (int)floorf((tx + 14.6f) * s));
    const int iy0 = max(0,      (int)ceilf ((ty - 29.6f) * s));
    const int iy1 = min(NT - 1, (int)floorf((ty + 14.6f) * s));

    const int seg = (threadIdx.x >> 5) & (SPLIT - 1);
    const float2 v = make_float2(xv, yv);
    for (int i = ix0; i <= ix1; i++)
        for (int j = iy0; j <= iy1; j++) {
            const int id2 = (((b * NT + i) * NT + j) * SPLIT) + seg;
            const int pos = atomicAdd(&g_cnt[id2 * 32], 1);
            if (pos < SEGCAP) g_bucket[(size_t)id2 * SEGCAP + pos] = v;
        }
}

// ---------------------------------------------------------------------------
// Persistent banded accumulator. Each CTA loops: grab segment ticket,
// decode (b,ti,tj,s), process its bucket segment with the register-prefetch
// + own-table + 4x4x16-replica scheme, write 16x16 partial. Empty segments
// cost one atomic + one LDG + 256 zero stores.
__global__ void __launch_bounds__(256, 4)
tile_kernel(const float* __restrict__ bins)
{
    __shared__ float binsS[MDIM];
    __shared__ float pool[2 * BUF * CPAD];   // kxT | kyT ; reused as red
    __shared__ int   ssel;
    float* kxT = pool;
    float* kyT = pool + BUF * CPAD;

    const int tid = threadIdx.x;
    binsS[tid] = bins[tid];
    __syncthreads();

    const float h    = binsS[1] - binsS[0];
    const float cexp = -0.72134752044f / (h * h);   // -0.5*log2(e)/h^2

    const int sub  = tid & 15;
    const int rrep = tid >> 4;
    const int bi4  = (sub & 3) * 4;
    const int bj4  = (sub >> 2) * 4;
    const int oi   = tid >> 4;
    const int oj   = tid & 15;
    const int sub2 = (oi >> 2) | ((oj >> 2) << 2);
    const int q2   = (oi & 3) * 4 + (oj & 3);

    for (;;) {
        if (tid == 0) ssel = atomicAdd(&g_ticket, 1);
        __syncthreads();
        const int seg = ssel;
        __syncthreads();                 // ssel free for next overwrite
        if (seg >= NSEG) break;          // uniform exit

        // seg = ((b*NT+ti)*NT+tj)*SPLIT + s
        const int s  = seg & (SPLIT - 1);
        int q        = seg >> 3;
        const int tj = q & (NT - 1);  q >>= 4;
        const int ti = q & (NT - 1);
        const int b  = q >> 4;
        const int i0 = ti * TILE;
        const int j0 = tj * TILE;
        float* gp = g_part + ((size_t)(b * SPLIT + s) * MDIM + i0) * MDIM + j0;

        const int c = min(g_cnt[seg * 32], SEGCAP);
        if (c == 0) {                    // cheap empty path
            gp[oi * MDIM + oj] = 0.f;
            continue;
        }

        const float* sbx = binsS + i0;
        const float* sby = binsS + j0;
        const float2* __restrict__ bk = g_bucket + (size_t)seg * SEGCAP;

        float acc[16];
#pragma unroll
        for (int qq = 0; qq < 16; qq++) acc[qq] = 0.f;

        float2 nv = make_float2(0.f, 0.f);
        if (tid < c) nv = __ldg(bk + tid);

        for (int base = 0; base < c; base += BUF) {
            const int cc = min(BUF, c - base);
            const float2 v = nv;
            const int nb = base + BUF;
            if (nb + tid < c) nv = __ldg(bk + nb + tid);  // prefetch

            if (tid < cc) {
                float* rx = kxT + tid * CPAD;
                float* ry = kyT + tid * CPAD;
#pragma unroll
                for (int k0 = 0; k0 < TILE; k0 += 4) {
                    float4 a4, e4;
                    float d;
                    d = v.x - sbx[k0 + 0]; a4.x = ex2f(cexp * d * d);
                    d = v.x - sbx[k0 + 1]; a4.y = ex2f(cexp * d * d);
                    d = v.x - sbx[k0 + 2]; a4.z = ex2f(cexp * d * d);
                    d = v.x - sbx[k0 + 3]; a4.w = ex2f(cexp * d * d);
                    d = v.y - sby[k0 + 0]; e4.x = ex2f(cexp * d * d);
                    d = v.y - sby[k0 + 1]; e4.y = ex2f(cexp * d * d);
                    d = v.y - sby[k0 + 2]; e4.z = ex2f(cexp * d * d);
                    d = v.y - sby[k0 + 3]; e4.w = ex2f(cexp * d * d);
                    *(float4*)(rx + k0) = a4;
                    *(float4*)(ry + k0) = e4;
                }
            }
            __syncthreads();

            int p = rrep;
            for (; p + 16 < cc; p += 32) {
                const float4 kx0 = *(const float4*)(kxT + p * CPAD + bi4);
                const float4 ky0 = *(const float4*)(kyT + p * CPAD + bj4);
                const float4 kx1 = *(const float4*)(kxT + (p + 16) * CPAD + bi4);
                const float4 ky1 = *(const float4*)(kyT + (p + 16) * CPAD + bj4);
                acc[ 0] += kx0.x * ky0.x;  acc[ 1] += kx0.x * ky0.y;
                acc[ 2] += kx0.x * ky0.z;  acc[ 3] += kx0.x * ky0.w;
                acc[ 4] += kx0.y * ky0.x;  acc[ 5] += kx0.y * ky0.y;
                acc[ 6] += kx0.y * ky0.z;  acc[ 7] += kx0.y * ky0.w;
                acc[ 8] += kx0.z * ky0.x;  acc[ 9] += kx0.z * ky0.y;
                acc[10] += kx0.z * ky0.z;  acc[11] += kx0.z * ky0.w;
                acc[12] += kx0.w * ky0.x;  acc[13] += kx0.w * ky0.y;
                acc[14] += kx0.w * ky0.z;  acc[15] += kx0.w * ky0.w;
                acc[ 0] += kx1.x * ky1.x;  acc[ 1] += kx1.x * ky1.y;
                acc[ 2] += kx1.x * ky1.z;  acc[ 3] += kx1.x * ky1.w;
                acc[ 4] += kx1.y * ky1.x;  acc[ 5] += kx1.y * ky1.y;
                acc[ 6] += kx1.y * ky1.z;  acc[ 7] += kx1.y * ky1.w;
                acc[ 8] += kx1.z * ky1.x;  acc[ 9] += kx1.z * ky1.y;
                acc[10] += kx1.z * ky1.z;  acc[11] += kx1.z * ky1.w;
                acc[12] += kx1.w * ky1.x;  acc[13] += kx1.w * ky1.y;
                acc[14] += kx1.w * ky1.z;  acc[15] += kx1.w * ky1.w;
            }
            if (p < cc) {
                const float4 kx = *(const float4*)(kxT + p * CPAD + bi4);
                const float4 ky = *(const float4*)(kyT + p * CPAD + bj4);
                acc[ 0] += kx.x * ky.x;  acc[ 1] += kx.x * ky.y;
                acc[ 2] += kx.x * ky.z;  acc[ 3] += kx.x * ky.w;
                acc[ 4] += kx.y * ky.x;  acc[ 5] += kx.y * ky.y;
                acc[ 6] += kx.y * ky.z;  acc[ 7] += kx.y * ky.w;
                acc[ 8] += kx.z * ky.x;  acc[ 9] += kx.z * ky.y;
                acc[10] += kx.z * ky.z;  acc[11] += kx.z * ky.w;
                acc[12] += kx.w * ky.x;  acc[13] += kx.w * ky.y;
                acc[14] += kx.w * ky.z;  acc[15] += kx.w * ky.w;
            }
            __syncthreads();
        }

        // Reduce 16 replicas (fixed order). Reuse pool as red (16 KB).
        float* red = pool;
#pragma unroll
        for (int qq = 0; qq < 16; qq++)
            red[rrep * 256 + sub * 16 + qq] = acc[qq];
        __syncthreads();

        float v = 0.f;
#pragma unroll
        for (int rr = 0; rr < 16; rr++)
            v += red[rr * 256 + sub2 * 16 + q2];
        gp[oi * MDIM + oj] = v;
        __syncthreads();                 // red free before next table build
    }
}

// ---------------------------------------------------------------------------
// Fused reduce + normalize. 256 CTAs x 256 threads (all co-resident; 32 regs
// / 1KB smem -> far more resident slots than 256 CTAs, spin terminates).
__global__ void reduce_norm_kernel(float* __restrict__ out)
{
    const int t  = blockIdx.x * 256 + threadIdx.x;   // float4 index
    const int b  = (t * 4) / (MDIM * MDIM);
    const int ij = t - b * (MDIM * MDIM / 4);

    float4 v = make_float4(0.f, 0.f, 0.f, 0.f);
#pragma unroll
    for (int s = 0; s < SPLIT; s++) {
        const float4 p = ((const float4*)g_part)[(b * SPLIT + s) *
                                                 (MDIM * MDIM / 4) + ij];
        v.x += p.x; v.y += p.y; v.z += p.z; v.w += p.w;
    }

    __shared__ float sm[256];
    sm[threadIdx.x] = (v.x + v.y) + (v.z + v.w);
    __syncthreads();
    for (int off = 128; off > 0; off >>= 1) {
        if (threadIdx.x < off) sm[threadIdx.x] += sm[threadIdx.x + off];
        __syncthreads();
    }
    if (threadIdx.x == 0) {
        atomicAdd(&g_sum[b], sm[0]);
        __threadfence();                       // release g_sum before arrive
        atomicAdd(&g_done, 1);
        while (*(volatile int*)&g_done < (int)gridDim.x) { }
    }
    __syncthreads();

    const float sv  = *(volatile float*)&g_sum[b];
    const float inv = 1.0f / (sv + 1e-10f);
    v.x *= inv; v.y *= inv; v.z *= inv; v.w *= inv;
    ((float4*)out)[t] = v;
}

// ---------------------------------------------------------------------------
extern "C" void kernel_launch(void* const* d_in, const int* in_sizes, int n_in,
                              void* d_out, int out_size)
{
    const float* x    = (const float*)d_in[0];   // (B, N) f32
    const float* y    = (const float*)d_in[1];   // (B, N) f32
    const float* bins = (const float*)d_in[2];   // (M,)  f32

    const int N = in_sizes[0] / NBATCH;

    zero_kernel<<<(NSEG + 255) / 256, 256>>>();

    dim3 bgrid((N + 255) / 256, NBATCH);
    bin_kernel<<<bgrid, 256>>>(x, y, bins, N);

    tile_kernel<<<TGRID, 256>>>(bins);

    reduce_norm_kernel<<<NBATCH * MDIM * MDIM / 1024, 256>>>((float*)d_out);
}